// round 1
// baseline (speedup 1.0000x reference)
#include <cuda_runtime.h>
#include <math.h>

#define BB 4
#define SS 4096
#define DD 512

// Scratch for Q, K, V (relu(x@W^T + b)), fp32. Allocation-free rule -> __device__ globals.
__device__ float g_Q[BB * SS * DD];
__device__ float g_K[BB * SS * DD];
__device__ float g_V[BB * SS * DD];

// ---------------------------------------------------------------------------
// Kernel 1: fused QKV projection.  Y[m,n] = relu( sum_k X[m,k] * W[n,k] + b[n] )
// M = B*S = 16384, N = 512, K = 512.  Classic 128x128x8 SIMT SGEMM, 8x8 microtile.
// blockIdx.z selects (Wq,bq,g_Q) / (Wk,bk,g_K) / (Wv,bv,g_V).
// ---------------------------------------------------------------------------
__global__ __launch_bounds__(256, 2) void qkv_proj_kernel(
    const float* __restrict__ X,
    const float* __restrict__ Wq, const float* __restrict__ bq,
    const float* __restrict__ Wk, const float* __restrict__ bk,
    const float* __restrict__ Wv, const float* __restrict__ bv)
{
    const int pz = blockIdx.z;
    const float* __restrict__ W    = (pz == 0) ? Wq : (pz == 1) ? Wk : Wv;
    const float* __restrict__ bias = (pz == 0) ? bq : (pz == 1) ? bk : bv;
    float* __restrict__ Y          = (pz == 0) ? g_Q : (pz == 1) ? g_K : g_V;

    __shared__ __align__(16) float As[8][132];  // +4 pad: conflict-free STS
    __shared__ __align__(16) float Bs[8][132];

    const int tid  = threadIdx.x;
    const int row0 = blockIdx.y * 128;   // M block
    const int col0 = blockIdx.x * 128;   // N block
    const int tx   = tid & 15;           // 16 col-tiles
    const int ty   = tid >> 4;           // 16 row-tiles

    float acc[8][8];
#pragma unroll
    for (int i = 0; i < 8; i++)
#pragma unroll
        for (int j = 0; j < 8; j++) acc[i][j] = 0.0f;

    const int lrow = tid >> 1;        // 0..127
    const int lk4  = (tid & 1) * 4;   // 0 or 4

    for (int k0 = 0; k0 < DD; k0 += 8) {
        // prefetch into regs
        float4 xa = *(const float4*)(X + (size_t)(row0 + lrow) * DD + k0 + lk4);
        float4 wb = *(const float4*)(W + (size_t)(col0 + lrow) * DD + k0 + lk4);
        __syncthreads();  // protect previous tile's reads
        As[lk4 + 0][lrow] = xa.x; As[lk4 + 1][lrow] = xa.y;
        As[lk4 + 2][lrow] = xa.z; As[lk4 + 3][lrow] = xa.w;
        Bs[lk4 + 0][lrow] = wb.x; Bs[lk4 + 1][lrow] = wb.y;
        Bs[lk4 + 2][lrow] = wb.z; Bs[lk4 + 3][lrow] = wb.w;
        __syncthreads();
#pragma unroll
        for (int kk = 0; kk < 8; kk++) {
            float a[8], b[8];
            *(float4*)(a + 0) = *(const float4*)&As[kk][ty * 8 + 0];
            *(float4*)(a + 4) = *(const float4*)&As[kk][ty * 8 + 4];
            *(float4*)(b + 0) = *(const float4*)&Bs[kk][tx * 8 + 0];
            *(float4*)(b + 4) = *(const float4*)&Bs[kk][tx * 8 + 4];
#pragma unroll
            for (int i = 0; i < 8; i++)
#pragma unroll
                for (int j = 0; j < 8; j++) acc[i][j] += a[i] * b[j];
        }
    }

    // epilogue: bias + relu, vectorized stores
    float bj[8];
#pragma unroll
    for (int j = 0; j < 8; j++) bj[j] = bias[col0 + tx * 8 + j];

#pragma unroll
    for (int i = 0; i < 8; i++) {
        const int r = row0 + ty * 8 + i;
        float* yrow = Y + (size_t)r * DD + col0 + tx * 8;
        float4 o0, o1;
        float v;
        v = acc[i][0] + bj[0]; o0.x = v > 0.f ? v : 0.f;
        v = acc[i][1] + bj[1]; o0.y = v > 0.f ? v : 0.f;
        v = acc[i][2] + bj[2]; o0.z = v > 0.f ? v : 0.f;
        v = acc[i][3] + bj[3]; o0.w = v > 0.f ? v : 0.f;
        v = acc[i][4] + bj[4]; o1.x = v > 0.f ? v : 0.f;
        v = acc[i][5] + bj[5]; o1.y = v > 0.f ? v : 0.f;
        v = acc[i][6] + bj[6]; o1.z = v > 0.f ? v : 0.f;
        v = acc[i][7] + bj[7]; o1.w = v > 0.f ? v : 0.f;
        *(float4*)(yrow + 0) = o0;
        *(float4*)(yrow + 4) = o1;
    }
}

// ---------------------------------------------------------------------------
// Kernel 2: flash attention, fp32.
// Grid: (S/32, B).  CTA = 256 threads = 8 warps; warp owns 4 q-rows.
// Per lane: q dims {lane*4 + 128*j + c}, j=0..3, c=0..3 (register-resident, pre-scaled).
// K/V tiles (32 rows x 512) double in dynamic smem (128 KB), streamed per tile.
// Per key: 16-FMA/lane dot -> 5-step butterfly -> warp-uniform online softmax.
// ---------------------------------------------------------------------------
__device__ __forceinline__ float dot4(float4 a, float4 b) {
    return a.x * b.x + a.y * b.y + a.z * b.z + a.w * b.w;
}

__global__ __launch_bounds__(256, 1) void attn_kernel(float* __restrict__ Out)
{
    extern __shared__ __align__(16) float sm[];
    float* Ks = sm;            // [32][512]
    float* Vs = sm + 32 * DD;  // [32][512]

    const int tid   = threadIdx.x;
    const int lane  = tid & 31;
    const int warp  = tid >> 5;
    const int b     = blockIdx.y;
    const int qbase = blockIdx.x * 32 + warp * 4;
    const int lane4 = lane * 4;

    const float scale = 0.044194173824159216f;  // 1/sqrt(512)

    // load + pre-scale q fragments
    float4 q[4][4];
#pragma unroll
    for (int r = 0; r < 4; r++) {
        const float* qp = g_Q + ((size_t)b * SS + qbase + r) * DD + lane4;
#pragma unroll
        for (int j = 0; j < 4; j++) {
            float4 t = *(const float4*)(qp + j * 128);
            t.x *= scale; t.y *= scale; t.z *= scale; t.w *= scale;
            q[r][j] = t;
        }
    }

    float4 acc[4][4];
#pragma unroll
    for (int r = 0; r < 4; r++)
#pragma unroll
        for (int j = 0; j < 4; j++) acc[r][j] = make_float4(0.f, 0.f, 0.f, 0.f);

    float mrow[4], lrow[4];
#pragma unroll
    for (int r = 0; r < 4; r++) { mrow[r] = -INFINITY; lrow[r] = 0.0f; }

    const float* Kg = g_K + (size_t)b * SS * DD;
    const float* Vg = g_V + (size_t)b * SS * DD;

    for (int kt = 0; kt < SS; kt += 32) {
        __syncthreads();  // previous tile fully consumed
        const float4* ksrc = (const float4*)(Kg + (size_t)kt * DD);
        const float4* vsrc = (const float4*)(Vg + (size_t)kt * DD);
        float4* kdst = (float4*)Ks;
        float4* vdst = (float4*)Vs;
#pragma unroll 4
        for (int i = tid; i < 32 * DD / 4; i += 256) {
            kdst[i] = ksrc[i];
            vdst[i] = vsrc[i];
        }
        __syncthreads();

#pragma unroll 2
        for (int kk = 0; kk < 32; kk++) {
            const float* kr = Ks + kk * DD + lane4;
            float4 k0 = *(const float4*)(kr + 0);
            float4 k1 = *(const float4*)(kr + 128);
            float4 k2 = *(const float4*)(kr + 256);
            float4 k3 = *(const float4*)(kr + 384);

            float s[4];
#pragma unroll
            for (int r = 0; r < 4; r++)
                s[r] = dot4(q[r][0], k0) + dot4(q[r][1], k1) +
                       dot4(q[r][2], k2) + dot4(q[r][3], k3);

#pragma unroll
            for (int off = 16; off > 0; off >>= 1) {
#pragma unroll
                for (int r = 0; r < 4; r++)
                    s[r] += __shfl_xor_sync(0xFFFFFFFFu, s[r], off);
            }
            // s[r] now warp-uniform

            const float* vr = Vs + kk * DD + lane4;
            float4 v0 = *(const float4*)(vr + 0);
            float4 v1 = *(const float4*)(vr + 128);
            float4 v2 = *(const float4*)(vr + 256);
            float4 v3 = *(const float4*)(vr + 384);

#pragma unroll
            for (int r = 0; r < 4; r++) {
                if (s[r] > mrow[r]) {  // warp-uniform, rare (~ln S times total)
                    float c = __expf(mrow[r] - s[r]);  // exp(-inf)=0 on first hit
                    lrow[r] *= c;
#pragma unroll
                    for (int j = 0; j < 4; j++) {
                        acc[r][j].x *= c; acc[r][j].y *= c;
                        acc[r][j].z *= c; acc[r][j].w *= c;
                    }
                    mrow[r] = s[r];
                }
                float pe = __expf(s[r] - mrow[r]);
                lrow[r] += pe;
                acc[r][0].x += pe * v0.x; acc[r][0].y += pe * v0.y;
                acc[r][0].z += pe * v0.z; acc[r][0].w += pe * v0.w;
                acc[r][1].x += pe * v1.x; acc[r][1].y += pe * v1.y;
                acc[r][1].z += pe * v1.z; acc[r][1].w += pe * v1.w;
                acc[r][2].x += pe * v2.x; acc[r][2].y += pe * v2.y;
                acc[r][2].z += pe * v2.z; acc[r][2].w += pe * v2.w;
                acc[r][3].x += pe * v3.x; acc[r][3].y += pe * v3.y;
                acc[r][3].z += pe * v3.z; acc[r][3].w += pe * v3.w;
            }
        }
    }

    // epilogue: normalize + store (coalesced float4)
#pragma unroll
    for (int r = 0; r < 4; r++) {
        const float inv = 1.0f / lrow[r];
        float* op = Out + ((size_t)b * SS + qbase + r) * DD + lane4;
#pragma unroll
        for (int j = 0; j < 4; j++) {
            float4 o = acc[r][j];
            o.x *= inv; o.y *= inv; o.z *= inv; o.w *= inv;
            *(float4*)(op + j * 128) = o;
        }
    }
}

// ---------------------------------------------------------------------------
extern "C" void kernel_launch(void* const* d_in, const int* in_sizes, int n_in,
                              void* d_out, int out_size)
{
    const float* X  = (const float*)d_in[0];
    const float* Wq = (const float*)d_in[1];
    const float* bq = (const float*)d_in[2];
    const float* Wk = (const float*)d_in[3];
    const float* bk = (const float*)d_in[4];
    const float* Wv = (const float*)d_in[5];
    const float* bv = (const float*)d_in[6];
    float* Out = (float*)d_out;

    const int attn_smem = 2 * 32 * DD * (int)sizeof(float);  // 128 KB
    cudaFuncSetAttribute(attn_kernel, cudaFuncAttributeMaxDynamicSharedMemorySize,
                         attn_smem);

    dim3 gp(DD / 128, (BB * SS) / 128, 3);
    qkv_proj_kernel<<<gp, 256>>>(X, Wq, bq, Wk, bk, Wv, bv);

    dim3 ga(SS / 32, BB);
    attn_kernel<<<ga, 256, attn_smem>>>(Out);
}